// round 15
// baseline (speedup 1.0000x reference)
#include <cuda_runtime.h>
#include <cuda_fp16.h>

// Problem constants (fixed by the dataset)
#define NI 6
#define CC 64
#define HI 224
#define WI 400
#define DD 8
#define HH 128
#define WW 128
#define PP (DD*HH*WW)          // 131072 voxels
#define VOXEL 0.4f

// Padded NHWC image: 2-pixel border keeps clamped corner-00 offsets in-bounds.
#define HP (HI + 4)            // 228
#define WP (WI + 4)            // 404

// fp16 NHWC with border: 70.7 MB (__device__ bss, zeroed).
// Kept L2-resident via evict_last 256-bit STORE hints.
__device__ __align__(256) __half g_img[(size_t)NI*HP*WP*CC];

#define T_STRIDE 401           // smem row stride (floats), odd -> low conflicts
#define SMEM_BYTES (64 * T_STRIDE * 4)   // 102,656 B dynamic

// ---------------------------------------------------------------------------
// cache-policy memory helpers. sm_103a ptxas: L2::evict_last requires 256-bit
// shapes (.v8.b32 / .v4.b64) -> 32B store. .cs has no such restriction.
// ---------------------------------------------------------------------------
__device__ __forceinline__ void st_evict_last_v8(void* p, uint4 a, uint4 b) {
    asm volatile("st.global.L2::evict_last.v8.b32 [%0], {%1,%2,%3,%4,%5,%6,%7,%8};"
                 :: "l"(p), "r"(a.x), "r"(a.y), "r"(a.z), "r"(a.w),
                    "r"(b.x), "r"(b.y), "r"(b.z), "r"(b.w) : "memory");
}
__device__ __forceinline__ void st_stream_v4(void* p, float4 v) {
    asm volatile("st.global.cs.v4.f32 [%0], {%1,%2,%3,%4};"
                 :: "l"(p), "f"(v.x), "f"(v.y), "f"(v.z), "f"(v.w) : "memory");
}

// ---------------------------------------------------------------------------
// Kernel 1: NCHW fp32 -> padded NHWC fp16 transpose.
// Block = one (n, h): 64 channels x FULL 400-pixel row. Each channel-plane
// row (1600B contiguous) is read once by one block as float4s -> maximal
// DRAM page locality (prior w-tiled versions split rows across 7 blocks and
// stalled at 55% DRAM). 1344 blocks, 512 threads, 102.7KB dynamic smem.
// Write: threads 0..399 emit 4 x 32B evict_last stores; warp lanes share q
// -> conflict-free smem column gathers, 1KB contiguous store per warp.
// ---------------------------------------------------------------------------
__global__ __launch_bounds__(512) void nchw_to_nhwc_kernel(const float* __restrict__ in) {
    extern __shared__ float tile[];   // [64][T_STRIDE]
    int h = blockIdx.x;               // 0..223
    int n = blockIdx.y;               // 0..5
    int tid = threadIdx.x;            // 0..511

    const float* src0 = in + (size_t)n*CC*HI*WI + (size_t)h*WI;
    // 64 planes x 100 float4 = 6400 loads, ~12.5 per thread
    #pragma unroll
    for (int it = 0; it < 13; it++) {
        int i = tid + it*512;
        if (i < 6400) {
            int c = i / 100;
            int j = i - c*100;
            float4 v = __ldcs(reinterpret_cast<const float4*>(src0 + (size_t)c*HI*WI) + j);
            float* dst = tile + c*T_STRIDE + j*4;
            dst[0] = v.x; dst[1] = v.y; dst[2] = v.z; dst[3] = v.w;
        }
    }
    __syncthreads();

    if (tid < WI) {
        int pix = tid;
        __half* gdst = g_img + (((size_t)n*HP + (h+2))*WP + (pix+2))*CC;
        #pragma unroll
        for (int q = 0; q < 4; q++) {
            const float* col = tile + (q*16)*T_STRIDE + pix;
            uint4 lo, hi;
            __half2 t;
            t = __floats2half2_rn(col[0*T_STRIDE],  col[1*T_STRIDE]);  lo.x = *reinterpret_cast<unsigned*>(&t);
            t = __floats2half2_rn(col[2*T_STRIDE],  col[3*T_STRIDE]);  lo.y = *reinterpret_cast<unsigned*>(&t);
            t = __floats2half2_rn(col[4*T_STRIDE],  col[5*T_STRIDE]);  lo.z = *reinterpret_cast<unsigned*>(&t);
            t = __floats2half2_rn(col[6*T_STRIDE],  col[7*T_STRIDE]);  lo.w = *reinterpret_cast<unsigned*>(&t);
            t = __floats2half2_rn(col[8*T_STRIDE],  col[9*T_STRIDE]);  hi.x = *reinterpret_cast<unsigned*>(&t);
            t = __floats2half2_rn(col[10*T_STRIDE], col[11*T_STRIDE]); hi.y = *reinterpret_cast<unsigned*>(&t);
            t = __floats2half2_rn(col[12*T_STRIDE], col[13*T_STRIDE]); hi.z = *reinterpret_cast<unsigned*>(&t);
            t = __floats2half2_rn(col[14*T_STRIDE], col[15*T_STRIDE]); hi.w = *reinterpret_cast<unsigned*>(&t);
            st_evict_last_v8(gdst + q*16, lo, hi);
        }
    }
}

// ---------------------------------------------------------------------------
// packed f32x2 helpers (Blackwell add.rn.f32x2: one instr = 2 fp32 adds)
// ---------------------------------------------------------------------------
__device__ __forceinline__ unsigned long long f32x2_pack(float lo, float hi) {
    unsigned long long r;
    asm("mov.b64 %0, {%1, %2};" : "=l"(r) : "r"(__float_as_uint(lo)), "r"(__float_as_uint(hi)));
    return r;
}
__device__ __forceinline__ void f32x2_unpack(unsigned long long v, float& lo, float& hi) {
    unsigned a, b;
    asm("mov.b64 {%0, %1}, %2;" : "=r"(a), "=r"(b) : "l"(v));
    lo = __uint_as_float(a); hi = __uint_as_float(b);
}
__device__ __forceinline__ unsigned long long f32x2_add(unsigned long long a, unsigned long long b) {
    unsigned long long r;
    asm("add.rn.f32x2 %0, %1, %2;" : "=l"(r) : "l"(a), "l"(b));
    return r;
}

// ---------------------------------------------------------------------------
// Kernel 2: projection+sampling (unchanged from R11 best: ~16.5us).
// ---------------------------------------------------------------------------
__device__ __forceinline__ void blend_cam(unsigned long long acc[4],
                                          const uint4& q00, const uint4& q10,
                                          const uint4& q01, const uint4& q11,
                                          unsigned wa, unsigned wb) {
    __half2 pa = *reinterpret_cast<const __half2*>(&wa);
    __half2 pb = *reinterpret_cast<const __half2*>(&wb);
    __half2 hw00 = __low2half2(pa);
    __half2 hw10 = __high2half2(pa);
    __half2 hw01 = __low2half2(pb);
    __half2 hw11 = __high2half2(pb);

    const __half2* a00 = reinterpret_cast<const __half2*>(&q00);
    const __half2* a10 = reinterpret_cast<const __half2*>(&q10);
    const __half2* a01 = reinterpret_cast<const __half2*>(&q01);
    const __half2* a11 = reinterpret_cast<const __half2*>(&q11);

    #pragma unroll
    for (int j = 0; j < 4; j++) {
        __half2 s = __hmul2(hw00, a00[j]);
        s = __hfma2(hw10, a10[j], s);
        s = __hfma2(hw01, a01[j], s);
        s = __hfma2(hw11, a11[j], s);
        float2 f = __half22float2(s);
        acc[j] = f32x2_add(acc[j], f32x2_pack(f.x, f.y));
    }
}

__global__ __launch_bounds__(256) void project_kernel(const float* __restrict__ K,
                                                      const float* __restrict__ R,
                                                      const float* __restrict__ T,
                                                      float* __restrict__ out) {
    __shared__ float cams[NI*12];
    __shared__ float st[CC][33];   // padded: only cols 0..31 used

    int tid = threadIdx.x;
    // fold K@R (9) and K@t (3) per camera, 72 values
    if (tid < NI*12) {
        int n = tid / 12;
        int j = tid - n*12;
        const float* k = K + n*9;
        float val;
        if (j < 9) {
            int i = j / 3, c = j - 3*i;
            val = k[i*3+0]*__ldg(R + n*9 + 0 + c)
                + k[i*3+1]*__ldg(R + n*9 + 3 + c)
                + k[i*3+2]*__ldg(R + n*9 + 6 + c);
        } else {
            int i = j - 9;
            val = k[i*3+0]*__ldg(T + n*3 + 0)
                + k[i*3+1]*__ldg(T + n*3 + 1)
                + k[i*3+2]*__ldg(T + n*3 + 2);
        }
        cams[tid] = val;
    }
    __syncthreads();

    int warp = tid >> 5;
    int lane = tid & 31;
    int vsel = lane >> 3;          // voxel within warp
    int cb   = (lane & 7) * 8;     // channel base (8 channels per lane)

    int p = blockIdx.x * 32 + warp * 4 + vsel;
    int h = p >> 10;
    int w = (p >> 3) & 127;
    int d = p & 7;

    float px = ((float)h - (HH - 1) * 0.5f) * VOXEL;
    float py = ((float)w - (WW - 1) * 0.5f) * VOXEL;
    float pz = ((float)d - (DD - 1) * 0.5f) * VOXEL;

    // ---- geometry phase: lane = vsel*8 + c handles (own voxel, camera c) ----
    unsigned gOff = 0;             // 0 == skip
    unsigned gWA = 0, gWB = 0;
    {
        int c = lane & 7;
        if (c < NI) {
            const float* m = cams + c*12;
            float X = m[0]*px + m[1]*py + m[2]*pz + m[9];
            float Y = m[3]*px + m[4]*py + m[5]*pz + m[10];
            float Z = m[6]*px + m[7]*py + m[8]*pz + m[11];
            if (Z >= 0.1f) {
                float u = __fdividef(X, Z);
                float v = __fdividef(Y, Z);
                // grid_sample-style coordinate mangling (matches reference;
                // +/-10 clamps dropped: they only alter already-masked taps)
                float xs = v * ((float)WI / (float)(HI - 1)) - 0.5f;
                float ys = u * ((float)HI / (float)(WI - 1)) - 0.5f;
                float x0f = floorf(xs);
                float y0f = floorf(ys);
                float wx = xs - x0f;
                float wy = ys - y0f;
                int x0 = (int)x0f;
                int y0 = (int)y0f;
                bool vx0 = (x0 >= 0)  && (x0 < WI);
                bool vx1 = (x0 >= -1) && (x0 < WI-1);
                bool vy0 = (y0 >= 0)  && (y0 < HI);
                bool vy1 = (y0 >= -1) && (y0 < HI-1);
                unsigned f = (vx0 && vy0 ? 1u : 0u)
                           | (vx1 && vy0 ? 2u : 0u)
                           | (vx0 && vy1 ? 4u : 0u)
                           | (vx1 && vy1 ? 8u : 0u);
                if (f) {
                    int px0 = min(max(x0 + 2, 0), WP - 2);
                    int py0 = min(max(y0 + 2, 0), HP - 2);
                    gOff = (unsigned)((c*HP + py0)*WP + px0) | (f << 20);
                    const float inv_n = 1.0f / (float)NI;
                    float w00 = (1.0f - wx) * (1.0f - wy) * inv_n;
                    float w10 = wx * (1.0f - wy) * inv_n;
                    float w01 = (1.0f - wx) * wy * inv_n;
                    float w11 = wx * wy * inv_n;
                    __half2 a = __floats2half2_rn(w00, w10);
                    __half2 b = __floats2half2_rn(w01, w11);
                    gWA = *reinterpret_cast<unsigned*>(&a);
                    gWB = *reinterpret_cast<unsigned*>(&b);
                }
            }
        }
    }

    unsigned long long acc[4];
    #pragma unroll
    for (int j = 0; j < 4; j++) acc[j] = 0ull;

    const uint4 zero4 = make_uint4(0u, 0u, 0u, 0u);
    const __half* base = g_img + cb;
    int srcbase = lane & 24;

    #pragma unroll
    for (int nn = 0; nn < NI; nn += 2) {
        unsigned ow0 = __shfl_sync(0xFFFFFFFFu, gOff, srcbase + nn);
        unsigned wa0 = __shfl_sync(0xFFFFFFFFu, gWA,  srcbase + nn);
        unsigned wb0 = __shfl_sync(0xFFFFFFFFu, gWB,  srcbase + nn);
        unsigned ow1 = __shfl_sync(0xFFFFFFFFu, gOff, srcbase + nn + 1);
        unsigned wa1 = __shfl_sync(0xFFFFFFFFu, gWA,  srcbase + nn + 1);
        unsigned wb1 = __shfl_sync(0xFFFFFFFFu, gWB,  srcbase + nn + 1);

        if ((ow0 | ow1) == 0u) continue;  // uniform within 8-lane voxel group

        unsigned fl0 = ow0 >> 20;
        unsigned fl1 = ow1 >> 20;
        const __half* p0 = base + (size_t)(ow0 & 0xFFFFFu) * CC;
        const __half* p1 = base + (size_t)(ow1 & 0xFFFFFu) * CC;

        // issue all (up to 8) corner loads before any math -> 2x MLP
        uint4 a00 = (fl0 & 1u) ? __ldg(reinterpret_cast<const uint4*>(p0))                     : zero4;
        uint4 a10 = (fl0 & 2u) ? __ldg(reinterpret_cast<const uint4*>(p0 + CC))                : zero4;
        uint4 a01 = (fl0 & 4u) ? __ldg(reinterpret_cast<const uint4*>(p0 + (size_t)WP*CC))     : zero4;
        uint4 a11 = (fl0 & 8u) ? __ldg(reinterpret_cast<const uint4*>(p0 + (size_t)(WP+1)*CC)) : zero4;
        uint4 b00 = (fl1 & 1u) ? __ldg(reinterpret_cast<const uint4*>(p1))                     : zero4;
        uint4 b10 = (fl1 & 2u) ? __ldg(reinterpret_cast<const uint4*>(p1 + CC))                : zero4;
        uint4 b01 = (fl1 & 4u) ? __ldg(reinterpret_cast<const uint4*>(p1 + (size_t)WP*CC))     : zero4;
        uint4 b11 = (fl1 & 8u) ? __ldg(reinterpret_cast<const uint4*>(p1 + (size_t)(WP+1)*CC)) : zero4;

        if (ow0) blend_cam(acc, a00, a10, a01, a11, wa0, wb0);
        if (ow1) blend_cam(acc, b00, b10, b01, b11, wa1, wb1);
    }

    int vcol = warp * 4 + vsel;    // 0..31
    #pragma unroll
    for (int j = 0; j < 4; j++) {
        float lo, hi;
        f32x2_unpack(acc[j], lo, hi);
        st[cb + 2*j][vcol]     = lo;
        st[cb + 2*j + 1][vcol] = hi;
    }
    __syncthreads();

    // streaming write-out (never re-read; keep out of L2): float4 stores
    int p_base = blockIdx.x * 32;
    #pragma unroll
    for (int k = tid; k < CC*8; k += 256) {
        int c = k >> 3;
        int j = (k & 7) * 4;
        float4 v = make_float4(st[c][j], st[c][j+1], st[c][j+2], st[c][j+3]);
        st_stream_v4(out + (size_t)c * PP + p_base + j, v);
    }
}

// ---------------------------------------------------------------------------
extern "C" void kernel_launch(void* const* d_in, const int* in_sizes, int n_in,
                              void* d_out, int out_size) {
    const float* images      = (const float*)d_in[0];
    const float* intrinsic   = (const float*)d_in[1];
    const float* rotation    = (const float*)d_in[2];
    const float* translation = (const float*)d_in[3];
    float* out = (float*)d_out;

    static int smem_set = 0;
    if (!smem_set) {
        cudaFuncSetAttribute(nchw_to_nhwc_kernel,
                             cudaFuncAttributeMaxDynamicSharedMemorySize, SMEM_BYTES);
        smem_set = 1;
    }

    dim3 tg(HI, NI);
    nchw_to_nhwc_kernel<<<tg, 512, SMEM_BYTES>>>(images);

    project_kernel<<<PP / 32, 256>>>(intrinsic, rotation, translation, out);
}

// round 16
// speedup vs baseline: 1.5722x; 1.5722x over previous
#include <cuda_runtime.h>
#include <cuda_fp16.h>

// Problem constants (fixed by the dataset)
#define NI 6
#define CC 64
#define HI 224
#define WI 400
#define DD 8
#define HH 128
#define WW 128
#define PP (DD*HH*WW)          // 131072 voxels
#define VOXEL 0.4f

// Padded NHWC image: 2-pixel border keeps clamped corner-00 offsets in-bounds.
#define HP (HI + 4)            // 228
#define WP (WI + 4)            // 404

// fp16 NHWC with border: 70.7 MB (__device__ bss, zeroed).
// Kept L2-resident via evict_last 256-bit STORE hints.
__device__ __align__(256) __half g_img[(size_t)NI*HP*WP*CC];

// Transpose uses 64x65 floats = 16.6KB, but requests 48KB dynamic smem to cap
// occupancy at 4 CTAs/SM: the 8-CTA config hits the documented cross-CTA
// L1tex-queue contention regime (8 front-batched LDGs x occ 8) and spreads
// per-CTA time ~1.5x over the DRAM bound.
#define T_USED  (64 * 65)
#define T_SMEM_REQ (48 * 1024)

// ---------------------------------------------------------------------------
// cache-policy memory helpers. sm_103a ptxas: L2::evict_last requires 256-bit
// shapes (.v8.b32 / .v4.b64) -> 32B store. .cs has no such restriction.
// ---------------------------------------------------------------------------
__device__ __forceinline__ void st_evict_last_v8(void* p, uint4 a, uint4 b) {
    asm volatile("st.global.L2::evict_last.v8.b32 [%0], {%1,%2,%3,%4,%5,%6,%7,%8};"
                 :: "l"(p), "r"(a.x), "r"(a.y), "r"(a.z), "r"(a.w),
                    "r"(b.x), "r"(b.y), "r"(b.z), "r"(b.w) : "memory");
}
__device__ __forceinline__ void st_stream_v4(void* p, float4 v) {
    asm volatile("st.global.cs.v4.f32 [%0], {%1,%2,%3,%4};"
                 :: "l"(p), "f"(v.x), "f"(v.y), "f"(v.z), "f"(v.w) : "memory");
}

// ---------------------------------------------------------------------------
// Kernel 1: NCHW fp32 -> padded NHWC fp16 transpose (R14 layout, occ-capped).
// Block = 64 channels x 1 h-row x 64 w-pixels, float2 input reads.
// Write: exactly one 32B evict_last store per thread (64 pix x 4 quads).
// ---------------------------------------------------------------------------
__global__ __launch_bounds__(256) void nchw_to_nhwc_kernel(const float* __restrict__ in) {
    extern __shared__ float tile[];   // [64][65] used
    int w0 = blockIdx.x << 6;       // width tile base: 0,64,...,384
    int h  = blockIdx.y;            // 0..223
    int n  = blockIdx.z;            // 0..5
    int tid = threadIdx.x;
    int tx = tid & 31;
    int ty = tid >> 5;

    const float* src = in + ((size_t)n*CC*HI + h)*WI + w0 + 2*tx;
    bool inw = (w0 + 2*tx < WI);    // WI even -> pair fully in or out
    #pragma unroll
    for (int i = 0; i < 8; i++) {
        int c = ty*8 + i;
        float2 v = inw ? __ldg(reinterpret_cast<const float2*>(src + (size_t)c*HI*WI))
                       : make_float2(0.0f, 0.0f);
        tile[c*65 + 2*tx]   = v.x;
        tile[c*65 + 2*tx+1] = v.y;
    }
    __syncthreads();

    {
        int pix = tid >> 2;         // 0..63
        int q   = tid & 3;          // 16-channel group
        int wp = w0 + pix;
        if (wp < WI) {
            int c0 = q * 16;
            const float* col = tile + c0*65 + pix;
            uint4 lo, hi;
            __half2 t;
            t = __floats2half2_rn(col[0*65],  col[1*65]);  lo.x = *reinterpret_cast<unsigned*>(&t);
            t = __floats2half2_rn(col[2*65],  col[3*65]);  lo.y = *reinterpret_cast<unsigned*>(&t);
            t = __floats2half2_rn(col[4*65],  col[5*65]);  lo.z = *reinterpret_cast<unsigned*>(&t);
            t = __floats2half2_rn(col[6*65],  col[7*65]);  lo.w = *reinterpret_cast<unsigned*>(&t);
            t = __floats2half2_rn(col[8*65],  col[9*65]);  hi.x = *reinterpret_cast<unsigned*>(&t);
            t = __floats2half2_rn(col[10*65], col[11*65]); hi.y = *reinterpret_cast<unsigned*>(&t);
            t = __floats2half2_rn(col[12*65], col[13*65]); hi.z = *reinterpret_cast<unsigned*>(&t);
            t = __floats2half2_rn(col[14*65], col[15*65]); hi.w = *reinterpret_cast<unsigned*>(&t);
            // padded layout: (n, h+2, w+2)
            st_evict_last_v8(g_img + ((((size_t)n*HP + (h+2))*WP + (wp+2))*CC + c0), lo, hi);
        }
    }
}

// ---------------------------------------------------------------------------
// packed f32x2 helpers (Blackwell add.rn.f32x2: one instr = 2 fp32 adds)
// ---------------------------------------------------------------------------
__device__ __forceinline__ unsigned long long f32x2_pack(float lo, float hi) {
    unsigned long long r;
    asm("mov.b64 %0, {%1, %2};" : "=l"(r) : "r"(__float_as_uint(lo)), "r"(__float_as_uint(hi)));
    return r;
}
__device__ __forceinline__ void f32x2_unpack(unsigned long long v, float& lo, float& hi) {
    unsigned a, b;
    asm("mov.b64 {%0, %1}, %2;" : "=r"(a), "=r"(b) : "l"(v));
    lo = __uint_as_float(a); hi = __uint_as_float(b);
}
__device__ __forceinline__ unsigned long long f32x2_add(unsigned long long a, unsigned long long b) {
    unsigned long long r;
    asm("add.rn.f32x2 %0, %1, %2;" : "=l"(r) : "l"(a), "l"(b));
    return r;
}

// ---------------------------------------------------------------------------
// Kernel 2: projection+sampling (unchanged from R11/R14 best: ~16.5us).
// ---------------------------------------------------------------------------
__device__ __forceinline__ void blend_cam(unsigned long long acc[4],
                                          const uint4& q00, const uint4& q10,
                                          const uint4& q01, const uint4& q11,
                                          unsigned wa, unsigned wb) {
    __half2 pa = *reinterpret_cast<const __half2*>(&wa);
    __half2 pb = *reinterpret_cast<const __half2*>(&wb);
    __half2 hw00 = __low2half2(pa);
    __half2 hw10 = __high2half2(pa);
    __half2 hw01 = __low2half2(pb);
    __half2 hw11 = __high2half2(pb);

    const __half2* a00 = reinterpret_cast<const __half2*>(&q00);
    const __half2* a10 = reinterpret_cast<const __half2*>(&q10);
    const __half2* a01 = reinterpret_cast<const __half2*>(&q01);
    const __half2* a11 = reinterpret_cast<const __half2*>(&q11);

    #pragma unroll
    for (int j = 0; j < 4; j++) {
        __half2 s = __hmul2(hw00, a00[j]);
        s = __hfma2(hw10, a10[j], s);
        s = __hfma2(hw01, a01[j], s);
        s = __hfma2(hw11, a11[j], s);
        float2 f = __half22float2(s);
        acc[j] = f32x2_add(acc[j], f32x2_pack(f.x, f.y));
    }
}

__global__ __launch_bounds__(256) void project_kernel(const float* __restrict__ K,
                                                      const float* __restrict__ R,
                                                      const float* __restrict__ T,
                                                      float* __restrict__ out) {
    __shared__ float cams[NI*12];
    __shared__ float st[CC][33];   // padded: only cols 0..31 used

    int tid = threadIdx.x;
    // fold K@R (9) and K@t (3) per camera, 72 values
    if (tid < NI*12) {
        int n = tid / 12;
        int j = tid - n*12;
        const float* k = K + n*9;
        float val;
        if (j < 9) {
            int i = j / 3, c = j - 3*i;
            val = k[i*3+0]*__ldg(R + n*9 + 0 + c)
                + k[i*3+1]*__ldg(R + n*9 + 3 + c)
                + k[i*3+2]*__ldg(R + n*9 + 6 + c);
        } else {
            int i = j - 9;
            val = k[i*3+0]*__ldg(T + n*3 + 0)
                + k[i*3+1]*__ldg(T + n*3 + 1)
                + k[i*3+2]*__ldg(T + n*3 + 2);
        }
        cams[tid] = val;
    }
    __syncthreads();

    int warp = tid >> 5;
    int lane = tid & 31;
    int vsel = lane >> 3;          // voxel within warp
    int cb   = (lane & 7) * 8;     // channel base (8 channels per lane)

    int p = blockIdx.x * 32 + warp * 4 + vsel;
    int h = p >> 10;
    int w = (p >> 3) & 127;
    int d = p & 7;

    float px = ((float)h - (HH - 1) * 0.5f) * VOXEL;
    float py = ((float)w - (WW - 1) * 0.5f) * VOXEL;
    float pz = ((float)d - (DD - 1) * 0.5f) * VOXEL;

    // ---- geometry phase: lane = vsel*8 + c handles (own voxel, camera c) ----
    unsigned gOff = 0;             // 0 == skip
    unsigned gWA = 0, gWB = 0;
    {
        int c = lane & 7;
        if (c < NI) {
            const float* m = cams + c*12;
            float X = m[0]*px + m[1]*py + m[2]*pz + m[9];
            float Y = m[3]*px + m[4]*py + m[5]*pz + m[10];
            float Z = m[6]*px + m[7]*py + m[8]*pz + m[11];
            if (Z >= 0.1f) {
                float u = __fdividef(X, Z);
                float v = __fdividef(Y, Z);
                // grid_sample-style coordinate mangling (matches reference;
                // +/-10 clamps dropped: they only alter already-masked taps)
                float xs = v * ((float)WI / (float)(HI - 1)) - 0.5f;
                float ys = u * ((float)HI / (float)(WI - 1)) - 0.5f;
                float x0f = floorf(xs);
                float y0f = floorf(ys);
                float wx = xs - x0f;
                float wy = ys - y0f;
                int x0 = (int)x0f;
                int y0 = (int)y0f;
                bool vx0 = (x0 >= 0)  && (x0 < WI);
                bool vx1 = (x0 >= -1) && (x0 < WI-1);
                bool vy0 = (y0 >= 0)  && (y0 < HI);
                bool vy1 = (y0 >= -1) && (y0 < HI-1);
                unsigned f = (vx0 && vy0 ? 1u : 0u)
                           | (vx1 && vy0 ? 2u : 0u)
                           | (vx0 && vy1 ? 4u : 0u)
                           | (vx1 && vy1 ? 8u : 0u);
                if (f) {
                    int px0 = min(max(x0 + 2, 0), WP - 2);
                    int py0 = min(max(y0 + 2, 0), HP - 2);
                    gOff = (unsigned)((c*HP + py0)*WP + px0) | (f << 20);
                    const float inv_n = 1.0f / (float)NI;
                    float w00 = (1.0f - wx) * (1.0f - wy) * inv_n;
                    float w10 = wx * (1.0f - wy) * inv_n;
                    float w01 = (1.0f - wx) * wy * inv_n;
                    float w11 = wx * wy * inv_n;
                    __half2 a = __floats2half2_rn(w00, w10);
                    __half2 b = __floats2half2_rn(w01, w11);
                    gWA = *reinterpret_cast<unsigned*>(&a);
                    gWB = *reinterpret_cast<unsigned*>(&b);
                }
            }
        }
    }

    unsigned long long acc[4];
    #pragma unroll
    for (int j = 0; j < 4; j++) acc[j] = 0ull;

    const uint4 zero4 = make_uint4(0u, 0u, 0u, 0u);
    const __half* base = g_img + cb;
    int srcbase = lane & 24;

    #pragma unroll
    for (int nn = 0; nn < NI; nn += 2) {
        unsigned ow0 = __shfl_sync(0xFFFFFFFFu, gOff, srcbase + nn);
        unsigned wa0 = __shfl_sync(0xFFFFFFFFu, gWA,  srcbase + nn);
        unsigned wb0 = __shfl_sync(0xFFFFFFFFu, gWB,  srcbase + nn);
        unsigned ow1 = __shfl_sync(0xFFFFFFFFu, gOff, srcbase + nn + 1);
        unsigned wa1 = __shfl_sync(0xFFFFFFFFu, gWA,  srcbase + nn + 1);
        unsigned wb1 = __shfl_sync(0xFFFFFFFFu, gWB,  srcbase + nn + 1);

        if ((ow0 | ow1) == 0u) continue;  // uniform within 8-lane voxel group

        unsigned fl0 = ow0 >> 20;
        unsigned fl1 = ow1 >> 20;
        const __half* p0 = base + (size_t)(ow0 & 0xFFFFFu) * CC;
        const __half* p1 = base + (size_t)(ow1 & 0xFFFFFu) * CC;

        // issue all (up to 8) corner loads before any math -> 2x MLP
        uint4 a00 = (fl0 & 1u) ? __ldg(reinterpret_cast<const uint4*>(p0))                     : zero4;
        uint4 a10 = (fl0 & 2u) ? __ldg(reinterpret_cast<const uint4*>(p0 + CC))                : zero4;
        uint4 a01 = (fl0 & 4u) ? __ldg(reinterpret_cast<const uint4*>(p0 + (size_t)WP*CC))     : zero4;
        uint4 a11 = (fl0 & 8u) ? __ldg(reinterpret_cast<const uint4*>(p0 + (size_t)(WP+1)*CC)) : zero4;
        uint4 b00 = (fl1 & 1u) ? __ldg(reinterpret_cast<const uint4*>(p1))                     : zero4;
        uint4 b10 = (fl1 & 2u) ? __ldg(reinterpret_cast<const uint4*>(p1 + CC))                : zero4;
        uint4 b01 = (fl1 & 4u) ? __ldg(reinterpret_cast<const uint4*>(p1 + (size_t)WP*CC))     : zero4;
        uint4 b11 = (fl1 & 8u) ? __ldg(reinterpret_cast<const uint4*>(p1 + (size_t)(WP+1)*CC)) : zero4;

        if (ow0) blend_cam(acc, a00, a10, a01, a11, wa0, wb0);
        if (ow1) blend_cam(acc, b00, b10, b01, b11, wa1, wb1);
    }

    int vcol = warp * 4 + vsel;    // 0..31
    #pragma unroll
    for (int j = 0; j < 4; j++) {
        float lo, hi;
        f32x2_unpack(acc[j], lo, hi);
        st[cb + 2*j][vcol]     = lo;
        st[cb + 2*j + 1][vcol] = hi;
    }
    __syncthreads();

    // streaming write-out (never re-read; keep out of L2): float4 stores
    int p_base = blockIdx.x * 32;
    #pragma unroll
    for (int k = tid; k < CC*8; k += 256) {
        int c = k >> 3;
        int j = (k & 7) * 4;
        float4 v = make_float4(st[c][j], st[c][j+1], st[c][j+2], st[c][j+3]);
        st_stream_v4(out + (size_t)c * PP + p_base + j, v);
    }
}

// ---------------------------------------------------------------------------
extern "C" void kernel_launch(void* const* d_in, const int* in_sizes, int n_in,
                              void* d_out, int out_size) {
    const float* images      = (const float*)d_in[0];
    const float* intrinsic   = (const float*)d_in[1];
    const float* rotation    = (const float*)d_in[2];
    const float* translation = (const float*)d_in[3];
    float* out = (float*)d_out;

    static int smem_set = 0;
    if (!smem_set) {
        cudaFuncSetAttribute(nchw_to_nhwc_kernel,
                             cudaFuncAttributeMaxDynamicSharedMemorySize, T_SMEM_REQ);
        smem_set = 1;
    }

    dim3 tg((WI + 63) / 64, HI, NI);
    nchw_to_nhwc_kernel<<<tg, 256, T_SMEM_REQ>>>(images);

    project_kernel<<<PP / 32, 256>>>(intrinsic, rotation, translation, out);
}

// round 17
// speedup vs baseline: 1.8317x; 1.1651x over previous
#include <cuda_runtime.h>
#include <cuda_fp16.h>

// Problem constants (fixed by the dataset)
#define NI 6
#define CC 64
#define HI 224
#define WI 400
#define DD 8
#define HH 128
#define WW 128
#define PP (DD*HH*WW)          // 131072 voxels
#define VOXEL 0.4f

// Padded NHWC image: 2-pixel border keeps clamped corner-00 offsets in-bounds.
#define HP (HI + 4)            // 228
#define WP (WI + 4)            // 404

// fp16 NHWC with border: 70.7 MB (__device__ bss, zeroed).
// Kept L2-resident via evict_last 256-bit STORE hints.
__device__ __align__(256) __half g_img[(size_t)NI*HP*WP*CC];

// ---------------------------------------------------------------------------
// cache-policy memory helpers. sm_103a ptxas: L2::evict_last requires 256-bit
// shapes (.v8.b32 / .v4.b64) -> 32B store. .cs has no such restriction.
// ---------------------------------------------------------------------------
__device__ __forceinline__ void st_evict_last_v8(void* p, uint4 a, uint4 b) {
    asm volatile("st.global.L2::evict_last.v8.b32 [%0], {%1,%2,%3,%4,%5,%6,%7,%8};"
                 :: "l"(p), "r"(a.x), "r"(a.y), "r"(a.z), "r"(a.w),
                    "r"(b.x), "r"(b.y), "r"(b.z), "r"(b.w) : "memory");
}
__device__ __forceinline__ void st_stream_v4(void* p, float4 v) {
    asm volatile("st.global.cs.v4.f32 [%0], {%1,%2,%3,%4};"
                 :: "l"(p), "f"(v.x), "f"(v.y), "f"(v.z), "f"(v.w) : "memory");
}

// ---------------------------------------------------------------------------
// Kernel 1: NCHW fp32 -> padded NHWC fp16 transpose (R14 config — measured
// floor across 5 tile variants). Block = 64ch x 1 row x 64 px, float2 reads.
// Signals PDL so the project kernel's prologue overlaps the final wave.
// ---------------------------------------------------------------------------
__global__ __launch_bounds__(256) void nchw_to_nhwc_kernel(const float* __restrict__ in) {
    __shared__ float tile[64][65];
    asm volatile("griddepcontrol.launch_dependents;");
    int w0 = blockIdx.x << 6;       // width tile base: 0,64,...,384
    int h  = blockIdx.y;            // 0..223
    int n  = blockIdx.z;            // 0..5
    int tid = threadIdx.x;
    int tx = tid & 31;
    int ty = tid >> 5;

    const float* src = in + ((size_t)n*CC*HI + h)*WI + w0 + 2*tx;
    bool inw = (w0 + 2*tx < WI);    // WI even -> pair fully in or out
    #pragma unroll
    for (int i = 0; i < 8; i++) {
        int c = ty*8 + i;
        float2 v = inw ? __ldg(reinterpret_cast<const float2*>(src + (size_t)c*HI*WI))
                       : make_float2(0.0f, 0.0f);
        tile[c][2*tx]   = v.x;
        tile[c][2*tx+1] = v.y;
    }
    __syncthreads();

    {
        int pix = tid >> 2;         // 0..63
        int q   = tid & 3;          // 16-channel group
        int wp = w0 + pix;
        if (wp < WI) {
            int c0 = q * 16;
            const float* col = &tile[c0][pix];
            uint4 lo, hi;
            __half2 t;
            t = __floats2half2_rn(col[0*65],  col[1*65]);  lo.x = *reinterpret_cast<unsigned*>(&t);
            t = __floats2half2_rn(col[2*65],  col[3*65]);  lo.y = *reinterpret_cast<unsigned*>(&t);
            t = __floats2half2_rn(col[4*65],  col[5*65]);  lo.z = *reinterpret_cast<unsigned*>(&t);
            t = __floats2half2_rn(col[6*65],  col[7*65]);  lo.w = *reinterpret_cast<unsigned*>(&t);
            t = __floats2half2_rn(col[8*65],  col[9*65]);  hi.x = *reinterpret_cast<unsigned*>(&t);
            t = __floats2half2_rn(col[10*65], col[11*65]); hi.y = *reinterpret_cast<unsigned*>(&t);
            t = __floats2half2_rn(col[12*65], col[13*65]); hi.z = *reinterpret_cast<unsigned*>(&t);
            t = __floats2half2_rn(col[14*65], col[15*65]); hi.w = *reinterpret_cast<unsigned*>(&t);
            // padded layout: (n, h+2, w+2)
            st_evict_last_v8(g_img + ((((size_t)n*HP + (h+2))*WP + (wp+2))*CC + c0), lo, hi);
        }
    }
}

// ---------------------------------------------------------------------------
// packed f32x2 helpers (Blackwell add.rn.f32x2: one instr = 2 fp32 adds)
// ---------------------------------------------------------------------------
__device__ __forceinline__ unsigned long long f32x2_pack(float lo, float hi) {
    unsigned long long r;
    asm("mov.b64 %0, {%1, %2};" : "=l"(r) : "r"(__float_as_uint(lo)), "r"(__float_as_uint(hi)));
    return r;
}
__device__ __forceinline__ void f32x2_unpack(unsigned long long v, float& lo, float& hi) {
    unsigned a, b;
    asm("mov.b64 {%0, %1}, %2;" : "=r"(a), "=r"(b) : "l"(v));
    lo = __uint_as_float(a); hi = __uint_as_float(b);
}
__device__ __forceinline__ unsigned long long f32x2_add(unsigned long long a, unsigned long long b) {
    unsigned long long r;
    asm("add.rn.f32x2 %0, %1, %2;" : "=l"(r) : "l"(a), "l"(b));
    return r;
}

// ---------------------------------------------------------------------------
// Kernel 2: projection+sampling. PDL: cam fold + geometry run BEFORE the
// griddepcontrol.wait (they depend only on K/R/T, not g_img), overlapping
// the transpose's tail; the wait guards the first g_img load.
// ---------------------------------------------------------------------------
__device__ __forceinline__ void blend_cam(unsigned long long acc[4],
                                          const uint4& q00, const uint4& q10,
                                          const uint4& q01, const uint4& q11,
                                          unsigned wa, unsigned wb) {
    __half2 pa = *reinterpret_cast<const __half2*>(&wa);
    __half2 pb = *reinterpret_cast<const __half2*>(&wb);
    __half2 hw00 = __low2half2(pa);
    __half2 hw10 = __high2half2(pa);
    __half2 hw01 = __low2half2(pb);
    __half2 hw11 = __high2half2(pb);

    const __half2* a00 = reinterpret_cast<const __half2*>(&q00);
    const __half2* a10 = reinterpret_cast<const __half2*>(&q10);
    const __half2* a01 = reinterpret_cast<const __half2*>(&q01);
    const __half2* a11 = reinterpret_cast<const __half2*>(&q11);

    #pragma unroll
    for (int j = 0; j < 4; j++) {
        __half2 s = __hmul2(hw00, a00[j]);
        s = __hfma2(hw10, a10[j], s);
        s = __hfma2(hw01, a01[j], s);
        s = __hfma2(hw11, a11[j], s);
        float2 f = __half22float2(s);
        acc[j] = f32x2_add(acc[j], f32x2_pack(f.x, f.y));
    }
}

__global__ __launch_bounds__(256) void project_kernel(const float* __restrict__ K,
                                                      const float* __restrict__ R,
                                                      const float* __restrict__ T,
                                                      float* __restrict__ out) {
    __shared__ float cams[NI*12];
    __shared__ float st[CC][33];   // padded: only cols 0..31 used

    int tid = threadIdx.x;
    // fold K@R (9) and K@t (3) per camera, 72 values (independent of g_img)
    if (tid < NI*12) {
        int n = tid / 12;
        int j = tid - n*12;
        const float* k = K + n*9;
        float val;
        if (j < 9) {
            int i = j / 3, c = j - 3*i;
            val = k[i*3+0]*__ldg(R + n*9 + 0 + c)
                + k[i*3+1]*__ldg(R + n*9 + 3 + c)
                + k[i*3+2]*__ldg(R + n*9 + 6 + c);
        } else {
            int i = j - 9;
            val = k[i*3+0]*__ldg(T + n*3 + 0)
                + k[i*3+1]*__ldg(T + n*3 + 1)
                + k[i*3+2]*__ldg(T + n*3 + 2);
        }
        cams[tid] = val;
    }
    __syncthreads();

    int warp = tid >> 5;
    int lane = tid & 31;
    int vsel = lane >> 3;          // voxel within warp
    int cb   = (lane & 7) * 8;     // channel base (8 channels per lane)

    int p = blockIdx.x * 32 + warp * 4 + vsel;
    int h = p >> 10;
    int w = (p >> 3) & 127;
    int d = p & 7;

    float px = ((float)h - (HH - 1) * 0.5f) * VOXEL;
    float py = ((float)w - (WW - 1) * 0.5f) * VOXEL;
    float pz = ((float)d - (DD - 1) * 0.5f) * VOXEL;

    // ---- geometry phase: lane = vsel*8 + c handles (own voxel, camera c) ----
    unsigned gOff = 0;             // 0 == skip
    unsigned gWA = 0, gWB = 0;
    {
        int c = lane & 7;
        if (c < NI) {
            const float* m = cams + c*12;
            float X = m[0]*px + m[1]*py + m[2]*pz + m[9];
            float Y = m[3]*px + m[4]*py + m[5]*pz + m[10];
            float Z = m[6]*px + m[7]*py + m[8]*pz + m[11];
            if (Z >= 0.1f) {
                float u = __fdividef(X, Z);
                float v = __fdividef(Y, Z);
                // grid_sample-style coordinate mangling (matches reference;
                // +/-10 clamps dropped: they only alter already-masked taps)
                float xs = v * ((float)WI / (float)(HI - 1)) - 0.5f;
                float ys = u * ((float)HI / (float)(WI - 1)) - 0.5f;
                float x0f = floorf(xs);
                float y0f = floorf(ys);
                float wx = xs - x0f;
                float wy = ys - y0f;
                int x0 = (int)x0f;
                int y0 = (int)y0f;
                bool vx0 = (x0 >= 0)  && (x0 < WI);
                bool vx1 = (x0 >= -1) && (x0 < WI-1);
                bool vy0 = (y0 >= 0)  && (y0 < HI);
                bool vy1 = (y0 >= -1) && (y0 < HI-1);
                unsigned f = (vx0 && vy0 ? 1u : 0u)
                           | (vx1 && vy0 ? 2u : 0u)
                           | (vx0 && vy1 ? 4u : 0u)
                           | (vx1 && vy1 ? 8u : 0u);
                if (f) {
                    int px0 = min(max(x0 + 2, 0), WP - 2);
                    int py0 = min(max(y0 + 2, 0), HP - 2);
                    gOff = (unsigned)((c*HP + py0)*WP + px0) | (f << 20);
                    const float inv_n = 1.0f / (float)NI;
                    float w00 = (1.0f - wx) * (1.0f - wy) * inv_n;
                    float w10 = wx * (1.0f - wy) * inv_n;
                    float w01 = (1.0f - wx) * wy * inv_n;
                    float w11 = wx * wy * inv_n;
                    __half2 a = __floats2half2_rn(w00, w10);
                    __half2 b = __floats2half2_rn(w01, w11);
                    gWA = *reinterpret_cast<unsigned*>(&a);
                    gWB = *reinterpret_cast<unsigned*>(&b);
                }
            }
        }
    }

    // g_img must be complete beyond this point (PDL barrier)
    asm volatile("griddepcontrol.wait;");

    unsigned long long acc[4];
    #pragma unroll
    for (int j = 0; j < 4; j++) acc[j] = 0ull;

    const uint4 zero4 = make_uint4(0u, 0u, 0u, 0u);
    const __half* base = g_img + cb;
    int srcbase = lane & 24;

    #pragma unroll
    for (int nn = 0; nn < NI; nn += 2) {
        unsigned ow0 = __shfl_sync(0xFFFFFFFFu, gOff, srcbase + nn);
        unsigned wa0 = __shfl_sync(0xFFFFFFFFu, gWA,  srcbase + nn);
        unsigned wb0 = __shfl_sync(0xFFFFFFFFu, gWB,  srcbase + nn);
        unsigned ow1 = __shfl_sync(0xFFFFFFFFu, gOff, srcbase + nn + 1);
        unsigned wa1 = __shfl_sync(0xFFFFFFFFu, gWA,  srcbase + nn + 1);
        unsigned wb1 = __shfl_sync(0xFFFFFFFFu, gWB,  srcbase + nn + 1);

        if ((ow0 | ow1) == 0u) continue;  // uniform within 8-lane voxel group

        unsigned fl0 = ow0 >> 20;
        unsigned fl1 = ow1 >> 20;
        const __half* p0 = base + (size_t)(ow0 & 0xFFFFFu) * CC;
        const __half* p1 = base + (size_t)(ow1 & 0xFFFFFu) * CC;

        // issue all (up to 8) corner loads before any math -> 2x MLP
        uint4 a00 = (fl0 & 1u) ? __ldg(reinterpret_cast<const uint4*>(p0))                     : zero4;
        uint4 a10 = (fl0 & 2u) ? __ldg(reinterpret_cast<const uint4*>(p0 + CC))                : zero4;
        uint4 a01 = (fl0 & 4u) ? __ldg(reinterpret_cast<const uint4*>(p0 + (size_t)WP*CC))     : zero4;
        uint4 a11 = (fl0 & 8u) ? __ldg(reinterpret_cast<const uint4*>(p0 + (size_t)(WP+1)*CC)) : zero4;
        uint4 b00 = (fl1 & 1u) ? __ldg(reinterpret_cast<const uint4*>(p1))                     : zero4;
        uint4 b10 = (fl1 & 2u) ? __ldg(reinterpret_cast<const uint4*>(p1 + CC))                : zero4;
        uint4 b01 = (fl1 & 4u) ? __ldg(reinterpret_cast<const uint4*>(p1 + (size_t)WP*CC))     : zero4;
        uint4 b11 = (fl1 & 8u) ? __ldg(reinterpret_cast<const uint4*>(p1 + (size_t)(WP+1)*CC)) : zero4;

        if (ow0) blend_cam(acc, a00, a10, a01, a11, wa0, wb0);
        if (ow1) blend_cam(acc, b00, b10, b01, b11, wa1, wb1);
    }

    int vcol = warp * 4 + vsel;    // 0..31
    #pragma unroll
    for (int j = 0; j < 4; j++) {
        float lo, hi;
        f32x2_unpack(acc[j], lo, hi);
        st[cb + 2*j][vcol]     = lo;
        st[cb + 2*j + 1][vcol] = hi;
    }
    __syncthreads();

    // streaming write-out (never re-read; keep out of L2): float4 stores
    int p_base = blockIdx.x * 32;
    #pragma unroll
    for (int k = tid; k < CC*8; k += 256) {
        int c = k >> 3;
        int j = (k & 7) * 4;
        float4 v = make_float4(st[c][j], st[c][j+1], st[c][j+2], st[c][j+3]);
        st_stream_v4(out + (size_t)c * PP + p_base + j, v);
    }
}

// ---------------------------------------------------------------------------
extern "C" void kernel_launch(void* const* d_in, const int* in_sizes, int n_in,
                              void* d_out, int out_size) {
    const float* images      = (const float*)d_in[0];
    const float* intrinsic   = (const float*)d_in[1];
    const float* rotation    = (const float*)d_in[2];
    const float* translation = (const float*)d_in[3];
    float* out = (float*)d_out;

    dim3 tg((WI + 63) / 64, HI, NI);
    nchw_to_nhwc_kernel<<<tg, 256>>>(images);

    // Project launched with programmatic stream serialization (PDL): its
    // prologue (cam fold + geometry) overlaps the transpose's tail; the
    // in-kernel griddepcontrol.wait guards the first g_img read.
    cudaLaunchConfig_t cfg = {};
    cfg.gridDim = dim3(PP / 32);
    cfg.blockDim = dim3(256);
    cfg.dynamicSmemBytes = 0;
    cudaLaunchAttribute attrs[1];
    attrs[0].id = cudaLaunchAttributeProgrammaticStreamSerialization;
    attrs[0].val.programmaticStreamSerializationAllowed = 1;
    cfg.attrs = attrs;
    cfg.numAttrs = 1;
    cudaLaunchKernelEx(&cfg, project_kernel, intrinsic, rotation, translation, out);
}